// round 7
// baseline (speedup 1.0000x reference)
#include <cuda_runtime.h>
#include <cuda_bf16.h>
#include <math.h>

#define EPS 1e-5f
#define F    128
#define F4   32
#define GMAX 1024
#define SEGS_PER_PHASE 16
#define NPHASE_MAIN 16            // covers segments [0, 256)
#define NPHASE      17            // + guard phase for segments [256, GMAX)
#define NBLK 296
#define BLKT 512

// Scratch (__device__ globals; no allocations allowed)
__device__ float        g_s1[GMAX * F];
__device__ float        g_s2[GMAX * F];
__device__ float        g_cnt[GMAX];
__device__ int          g_segstart[GMAX + 1];
__device__ unsigned int g_done[NPHASE];

// ---------------------------------------------------------------------------
// 0) zero accumulators + phase counters (must run every launch: graph replays)
// ---------------------------------------------------------------------------
__global__ void zero_kernel() {
    const int total = 2 * GMAX * F + GMAX + NPHASE;
    for (int i = blockIdx.x * blockDim.x + threadIdx.x; i < total;
         i += gridDim.x * blockDim.x) {
        if (i < GMAX * F)                 g_s1[i] = 0.f;
        else if (i < 2 * GMAX * F)        g_s2[i - GMAX * F] = 0.f;
        else if (i < 2 * GMAX * F + GMAX) g_cnt[i - 2 * GMAX * F] = 0.f;
        else                              g_done[i - 2 * GMAX * F - GMAX] = 0u;
    }
}

// ---------------------------------------------------------------------------
// 0b) segment start offsets: g_segstart[g] = lower_bound(batch, g)
// ---------------------------------------------------------------------------
__global__ void segstart_kernel(const int* __restrict__ batch, int N) {
    const int g = blockIdx.x * blockDim.x + threadIdx.x;
    if (g > GMAX) return;
    int lo = 0, hi = N;
    while (lo < hi) {
        const int mid = (lo + hi) >> 1;
        if (__ldg(&batch[mid]) < g) lo = mid + 1; else hi = mid;
    }
    g_segstart[g] = lo;
}

// ---------------------------------------------------------------------------
// 1) fused persistent kernel: per phase (16 segments ~= 64MB of x):
//    stats (cache x in L2) -> counting barrier -> normalize (x from L2/L1)
// ---------------------------------------------------------------------------
__global__ void __launch_bounds__(BLKT, 2) fused_kernel(
    const float* __restrict__ x, const int* __restrict__ batch,
    const float* __restrict__ gamma, const float* __restrict__ beta,
    float* __restrict__ out, int N)
{
    const int tid = threadIdx.x;
    const int bid = blockIdx.x;
    const int nb  = gridDim.x;
    const int f   = tid & (F - 1);   // stats: feature 0..127
    const int rl  = tid >> 7;        // stats: row lane 0..3
    const int c   = tid & 31;        // norm: float4 column (constant: stride 512 = 16*32)

    const float4* __restrict__ x4     = (const float4*)x;
    float4* __restrict__       out4   = (float4*)out;
    const float4 gm = __ldg(&((const float4*)gamma)[c]);
    const float4 bt = __ldg(&((const float4*)beta)[c]);

    // per-thread (segment -> mean4/rstd4) cache; seg ids increase monotonically
    int    cseg = -1;
    float4 cmean = {0.f, 0.f, 0.f, 0.f}, crstd = {0.f, 0.f, 0.f, 0.f};

    for (int p = 0; p < NPHASE; p++) {
        const int g0 = (p < NPHASE_MAIN) ? p * SEGS_PER_PHASE : NPHASE_MAIN * SEGS_PER_PHASE;
        const int g1 = (p < NPHASE_MAIN) ? g0 + SEGS_PER_PHASE : GMAX;
        const int r0 = g_segstart[g0];
        const int r1 = g_segstart[g1];
        const int nrows = r1 - r0;

        const int chunk = (nrows + nb - 1) / nb;
        const int my0 = r0 + bid * chunk;
        const int my1 = min(r1, my0 + chunk);

        // ---------------- stats over this block's row slice ----------------
        if (nrows > 0 && my0 < my1) {
            float s1 = 0.f, s2 = 0.f, cnt = 0.f;
            int cur = -1;
#define GN_FLUSH()                                                      \
            do {                                                        \
                if (cur >= 0) {                                         \
                    atomicAdd(&g_s1[cur * F + f], s1);                  \
                    atomicAdd(&g_s2[cur * F + f], s2);                  \
                    if (f == 0) atomicAdd(&g_cnt[cur], cnt);            \
                }                                                       \
            } while (0)
#define GN_PROC(SEG, V)                                                 \
            do {                                                        \
                if ((SEG) != cur) {                                     \
                    GN_FLUSH();                                         \
                    cur = (SEG); s1 = 0.f; s2 = 0.f; cnt = 0.f;         \
                }                                                       \
                s1 += (V); s2 += (V) * (V); cnt += 1.f;                 \
            } while (0)
            int r = my0 + rl;
            for (; r + 28 < my1; r += 32) {
                int   sg[8];
                float vv[8];
#pragma unroll
                for (int k = 0; k < 8; k++) sg[k] = __ldg(&batch[r + 4 * k]);
#pragma unroll
                for (int k = 0; k < 8; k++) vv[k] = x[(size_t)(r + 4 * k) * F + f];
#pragma unroll
                for (int k = 0; k < 8; k++) GN_PROC(sg[k], vv[k]);
            }
            for (; r < my1; r += 4) {
                const int   seg = __ldg(&batch[r]);
                const float v   = x[(size_t)r * F + f];
                GN_PROC(seg, v);
            }
            GN_FLUSH();
#undef GN_PROC
#undef GN_FLUSH
        }

        // ---------------- counting barrier for phase p ----------------
        __syncthreads();
        if (tid == 0) {
            __threadfence();
            atomicAdd(&g_done[p], 1u);
            while (atomicAdd(&g_done[p], 0u) < (unsigned)nb) __nanosleep(256);
        }
        __syncthreads();

        // ---------------- normalize this block's row slice ----------------
        if (nrows > 0 && my0 < my1) {
            const int e0 = my0 * F4;
            const int e1 = my1 * F4;
            int i = e0 + tid;
            for (; i + BLKT < e1; i += 2 * BLKT) {
                const int iA = i, iB = i + BLKT;
                const int sA = __ldg(&batch[iA >> 5]);
                const int sB = __ldg(&batch[iB >> 5]);
                const float4 vA = x4[iA];
                const float4 vB = x4[iB];

                if (sA != cseg) {
                    const float denom = fmaxf(g_cnt[sA], 1.f);
                    const float inv   = 1.0f / denom;
                    const float4 s1v  = *(const float4*)&g_s1[sA * F + 4 * c];
                    const float4 s2v  = *(const float4*)&g_s2[sA * F + 4 * c];
                    cmean.x = s1v.x * inv; cmean.y = s1v.y * inv;
                    cmean.z = s1v.z * inv; cmean.w = s1v.w * inv;
                    crstd.x = rsqrtf(fmaxf(s2v.x * inv - cmean.x * cmean.x, EPS) + EPS);
                    crstd.y = rsqrtf(fmaxf(s2v.y * inv - cmean.y * cmean.y, EPS) + EPS);
                    crstd.z = rsqrtf(fmaxf(s2v.z * inv - cmean.z * cmean.z, EPS) + EPS);
                    crstd.w = rsqrtf(fmaxf(s2v.w * inv - cmean.w * cmean.w, EPS) + EPS);
                    cseg = sA;
                }
                float4 o;
                o.x = (vA.x - cmean.x) * crstd.x * gm.x + bt.x;
                o.y = (vA.y - cmean.y) * crstd.y * gm.y + bt.y;
                o.z = (vA.z - cmean.z) * crstd.z * gm.z + bt.z;
                o.w = (vA.w - cmean.w) * crstd.w * gm.w + bt.w;
                __stcs(&out4[iA], o);

                if (sB != cseg) {
                    const float denom = fmaxf(g_cnt[sB], 1.f);
                    const float inv   = 1.0f / denom;
                    const float4 s1v  = *(const float4*)&g_s1[sB * F + 4 * c];
                    const float4 s2v  = *(const float4*)&g_s2[sB * F + 4 * c];
                    cmean.x = s1v.x * inv; cmean.y = s1v.y * inv;
                    cmean.z = s1v.z * inv; cmean.w = s1v.w * inv;
                    crstd.x = rsqrtf(fmaxf(s2v.x * inv - cmean.x * cmean.x, EPS) + EPS);
                    crstd.y = rsqrtf(fmaxf(s2v.y * inv - cmean.y * cmean.y, EPS) + EPS);
                    crstd.z = rsqrtf(fmaxf(s2v.z * inv - cmean.z * cmean.z, EPS) + EPS);
                    crstd.w = rsqrtf(fmaxf(s2v.w * inv - cmean.w * cmean.w, EPS) + EPS);
                    cseg = sB;
                }
                o.x = (vB.x - cmean.x) * crstd.x * gm.x + bt.x;
                o.y = (vB.y - cmean.y) * crstd.y * gm.y + bt.y;
                o.z = (vB.z - cmean.z) * crstd.z * gm.z + bt.z;
                o.w = (vB.w - cmean.w) * crstd.w * gm.w + bt.w;
                __stcs(&out4[iB], o);
            }
            for (; i < e1; i += BLKT) {
                const int seg = __ldg(&batch[i >> 5]);
                const float4 v = x4[i];
                if (seg != cseg) {
                    const float denom = fmaxf(g_cnt[seg], 1.f);
                    const float inv   = 1.0f / denom;
                    const float4 s1v  = *(const float4*)&g_s1[seg * F + 4 * c];
                    const float4 s2v  = *(const float4*)&g_s2[seg * F + 4 * c];
                    cmean.x = s1v.x * inv; cmean.y = s1v.y * inv;
                    cmean.z = s1v.z * inv; cmean.w = s1v.w * inv;
                    crstd.x = rsqrtf(fmaxf(s2v.x * inv - cmean.x * cmean.x, EPS) + EPS);
                    crstd.y = rsqrtf(fmaxf(s2v.y * inv - cmean.y * cmean.y, EPS) + EPS);
                    crstd.z = rsqrtf(fmaxf(s2v.z * inv - cmean.z * cmean.z, EPS) + EPS);
                    crstd.w = rsqrtf(fmaxf(s2v.w * inv - cmean.w * cmean.w, EPS) + EPS);
                    cseg = seg;
                }
                float4 o;
                o.x = (v.x - cmean.x) * crstd.x * gm.x + bt.x;
                o.y = (v.y - cmean.y) * crstd.y * gm.y + bt.y;
                o.z = (v.z - cmean.z) * crstd.z * gm.z + bt.z;
                o.w = (v.w - cmean.w) * crstd.w * gm.w + bt.w;
                __stcs(&out4[i], o);
            }
        }
    }
}

// ---------------------------------------------------------------------------
extern "C" void kernel_launch(void* const* d_in, const int* in_sizes, int n_in,
                              void* d_out, int out_size)
{
    const float* x     = (const float*)d_in[0];
    const float* gamma = (const float*)d_in[1];
    const float* beta  = (const float*)d_in[2];
    const int*   batch = (const int*)d_in[3];

    const int N = in_sizes[3];

    zero_kernel<<<256, 256>>>();
    segstart_kernel<<<(GMAX + 1 + 255) / 256, 256>>>(batch, N);
    fused_kernel<<<NBLK, BLKT>>>(x, batch, gamma, beta, (float*)d_out, N);
}

// round 9
// speedup vs baseline: 1.0456x; 1.0456x over previous
#include <cuda_runtime.h>
#include <cuda_bf16.h>
#include <math.h>

#define EPS 1e-5f
#define F    128
#define F4   32
#define GMAX 1024

// Scratch (__device__ globals; no allocations allowed)
__device__ float g_s1[GMAX * F];
__device__ float g_s2[GMAX * F];
__device__ float g_cnt[GMAX];
__device__ float g_mean[GMAX * F];
__device__ float g_rstd[GMAX * F];
__device__ int   g_segstart[GMAX + 1];

// ---------------------------------------------------------------------------
// 0) zero the accumulators (must run each launch: graph replays)
// ---------------------------------------------------------------------------
__global__ void zero_kernel() {
    int total = 2 * GMAX * F + GMAX;
    for (int i = blockIdx.x * blockDim.x + threadIdx.x; i < total;
         i += gridDim.x * blockDim.x) {
        if (i < GMAX * F)            g_s1[i] = 0.f;
        else if (i < 2 * GMAX * F)   g_s2[i - GMAX * F] = 0.f;
        else                         g_cnt[i - 2 * GMAX * F] = 0.f;
    }
}

// ---------------------------------------------------------------------------
// 0b) segment start offsets: g_segstart[g] = lower_bound(batch, g)
// ---------------------------------------------------------------------------
__global__ void segstart_kernel(const int* __restrict__ batch, int N) {
    const int g = blockIdx.x * blockDim.x + threadIdx.x;
    if (g > GMAX) return;
    int lo = 0, hi = N;
    while (lo < hi) {
        const int mid = (lo + hi) >> 1;
        if (__ldg(&batch[mid]) < g) lo = mid + 1; else hi = mid;
    }
    g_segstart[g] = lo;
}

// ---------------------------------------------------------------------------
// 1) per-segment sum/sumsq. batch sorted -> register accumulation, flush on
//    segment change. 512 threads = 4 row lanes x 128 features, 8 row-groups
//    prefetched per iteration.
// ---------------------------------------------------------------------------
__global__ void __launch_bounds__(512) stats_kernel(
    const float* __restrict__ x, const int* __restrict__ batch,
    int N, int rows_per_block)
{
    const int f  = threadIdx.x & (F - 1);
    const int rl = threadIdx.x >> 7;

    const int row0    = blockIdx.x * rows_per_block;
    const int row_end = min(N, row0 + rows_per_block);
    if (row0 >= N) return;

    float s1 = 0.f, s2 = 0.f, cnt = 0.f;
    int cur = -1;

#define GN_FLUSH()                                                      \
    do {                                                                \
        if (cur >= 0) {                                                 \
            atomicAdd(&g_s1[cur * F + f], s1);                          \
            atomicAdd(&g_s2[cur * F + f], s2);                          \
            if (f == 0) atomicAdd(&g_cnt[cur], cnt);                    \
        }                                                               \
    } while (0)

#define GN_PROC(SEG, V)                                                 \
    do {                                                                \
        if ((SEG) != cur) {                                             \
            GN_FLUSH();                                                 \
            cur = (SEG); s1 = 0.f; s2 = 0.f; cnt = 0.f;                 \
        }                                                               \
        s1 += (V); s2 += (V) * (V); cnt += 1.f;                         \
    } while (0)

    int r = row0 + rl;
    for (; r + 28 < row_end; r += 32) {
        int   sg[8];
        float vv[8];
#pragma unroll
        for (int k = 0; k < 8; k++) sg[k] = __ldg(&batch[r + 4 * k]);
#pragma unroll
        for (int k = 0; k < 8; k++) vv[k] = __ldcs(&x[(size_t)(r + 4 * k) * F + f]);
#pragma unroll
        for (int k = 0; k < 8; k++) GN_PROC(sg[k], vv[k]);
    }
    for (; r < row_end; r += 4) {
        const int   seg = __ldg(&batch[r]);
        const float v   = __ldcs(&x[(size_t)r * F + f]);
        GN_PROC(seg, v);
    }
    GN_FLUSH();
#undef GN_PROC
#undef GN_FLUSH
}

// ---------------------------------------------------------------------------
// 2) finalize: mean + rstd tables (L2-resident for pass 3)
// ---------------------------------------------------------------------------
__global__ void finalize_kernel() {
    int idx = blockIdx.x * blockDim.x + threadIdx.x;
    if (idx >= GMAX * F) return;
    const int g = idx >> 7;
    const float c     = g_cnt[g];
    const float denom = fmaxf(c, 1.f);
    const float mean  = g_s1[idx] / denom;
    float var = g_s2[idx] / denom - mean * mean;
    var = fmaxf(var, EPS);
    g_mean[idx] = mean;
    g_rstd[idx] = rsqrtf(var + EPS);
}

// ---------------------------------------------------------------------------
// 3) normalize: contiguous row range per block; per-thread register cache of
//    (seg, mean4, rstd4), advanced via g_segstart (no batch loads, no
//    dependent table loads in the hot loop). 8x front-batched float4 loads.
// ---------------------------------------------------------------------------
__global__ void __launch_bounds__(256) norm_kernel(
    const float4* __restrict__ x4,
    const float4* __restrict__ gamma4, const float4* __restrict__ beta4,
    float4* __restrict__ out4, int N, int rows_per_block)
{
    const int row0 = blockIdx.x * rows_per_block;
    const int row1 = min(N, row0 + rows_per_block);
    if (row0 >= row1) return;

    const int tid = threadIdx.x;
    const int c   = tid & 31;   // float4 column: invariant (stride 256 ≡ 0 mod 32)

    const float4 gm = __ldg(&gamma4[c]);
    const float4 bt = __ldg(&beta4[c]);
    const float4* __restrict__ mean4 = (const float4*)g_mean;
    const float4* __restrict__ rstd4 = (const float4*)g_rstd;

    // initial segment for row0: max seg with segstart[seg] <= row0
    int lo = 0, hi = GMAX - 1;
    while (lo < hi) {
        const int mid = (lo + hi + 1) >> 1;
        if (g_segstart[mid] <= row0) lo = mid; else hi = mid - 1;
    }
    int cseg   = lo;
    int segend = g_segstart[cseg + 1];
    float4 cm = __ldg(&mean4[cseg * F4 + c]);
    float4 cr = __ldg(&rstd4[cseg * F4 + c]);

#define GN_UPD(II)                                                       \
    do {                                                                 \
        const int row_ = (II) >> 5;                                      \
        if (row_ >= segend) {                                            \
            do { cseg++; segend = g_segstart[cseg + 1]; }                \
            while (row_ >= segend);                                      \
            cm = __ldg(&mean4[cseg * F4 + c]);                           \
            cr = __ldg(&rstd4[cseg * F4 + c]);                           \
        }                                                                \
    } while (0)

#define GN_OUT(II, V)                                                    \
    do {                                                                 \
        float4 o_;                                                       \
        o_.x = (V.x - cm.x) * cr.x * gm.x + bt.x;                        \
        o_.y = (V.y - cm.y) * cr.y * gm.y + bt.y;                        \
        o_.z = (V.z - cm.z) * cr.z * gm.z + bt.z;                        \
        o_.w = (V.w - cm.w) * cr.w * gm.w + bt.w;                        \
        __stcs(&out4[II], o_);                                           \
    } while (0)

    const int e0 = row0 * F4;
    const int e1 = row1 * F4;
    int i = e0 + tid;
    for (; i + 7 * 256 < e1; i += 8 * 256) {
        float4 v[8];
#pragma unroll
        for (int k = 0; k < 8; k++) v[k] = __ldcs(&x4[i + k * 256]);
#pragma unroll
        for (int k = 0; k < 8; k++) {
            const int ii = i + k * 256;
            GN_UPD(ii);
            GN_OUT(ii, v[k]);
        }
    }
    for (; i < e1; i += 256) {
        const float4 v = __ldcs(&x4[i]);
        GN_UPD(i);
        GN_OUT(i, v);
    }
#undef GN_UPD
#undef GN_OUT
}

// ---------------------------------------------------------------------------
extern "C" void kernel_launch(void* const* d_in, const int* in_sizes, int n_in,
                              void* d_out, int out_size)
{
    const float* x     = (const float*)d_in[0];
    const float* gamma = (const float*)d_in[1];
    const float* beta  = (const float*)d_in[2];
    const int*   batch = (const int*)d_in[3];

    const int N = in_sizes[3];

    zero_kernel<<<256, 256>>>();
    segstart_kernel<<<(GMAX + 1 + 255) / 256, 256>>>(batch, N);

    const int stat_blocks = 2368;       // 148 SMs * 16
    const int stat_rpb = (N + stat_blocks - 1) / stat_blocks;
    stats_kernel<<<stat_blocks, 512>>>(x, batch, N, stat_rpb);

    finalize_kernel<<<(GMAX * F + 255) / 256, 256>>>();

    const int norm_blocks = 1184;       // 148 SMs * 8, contiguous row chunks
    const int norm_rpb = (N + norm_blocks - 1) / norm_blocks;
    norm_kernel<<<norm_blocks, 256>>>((const float4*)x,
                                      (const float4*)gamma, (const float4*)beta,
                                      (float4*)d_out, N, norm_rpb);
}